// round 6
// baseline (speedup 1.0000x reference)
#include <cuda_runtime.h>
#include <cstdint>

// Degenerate conv (reference uses only x[:,0] and w[:,2]):
//   out(n,f,i,j) = bias[f] + sum_{a,b} w[f,2,a,b] * x[n,0,i+a,j+b]
//   x: (16,3,256,256) f32, w: (64,3,3,3) f32, b: (64,) f32
//   out: (16,64,254,254) f32
//
// Structure: 4 rows x 2 cols per thread (all stores warp-dense 256B),
// filter dim split 4 ways (16 filters/thread). Rows 252..253 via tail threads.
#define NB     16
#define F_OUT  64
#define F_Q    16
#define Hh     256
#define Ww     256
#define HO     254
#define WO     254
#define JP     (WO / 2)                  // 127 col-pairs (j even)
#define IB4    63                        // 4-row bands: i = 0,4,...,248
#define N_SP4  (NB * IB4 * JP)           // 128016 main spatial tiles
#define N_MAIN (N_SP4 * 4)               // 512064 (x4 filter quarters)
#define N_SPT  (NB * JP)                 // 2032 tail tiles (rows 252..253)
#define N_TAIL (N_SPT * 4)               // 8128
#define N_TOT  (N_MAIN + N_TAIL)         // 520192 = 4064 * 128 exactly

typedef unsigned long long u64;

// packed f32x2 FMA (Blackwell): d = a * w + c on both lanes
static __device__ __forceinline__ u64 ffma2(u64 a, u64 w, u64 c) {
    u64 d;
    asm("fma.rn.f32x2 %0, %1, %2, %3;" : "=l"(d) : "l"(a), "l"(w), "l"(c));
    return d;
}

static __device__ __forceinline__ u64 pack2(float lo, float hi) {
    u64 d;
    asm("mov.b64 %0, {%1, %2};" : "=l"(d) : "f"(lo), "f"(hi));
    return d;
}

__global__ __launch_bounds__(128) void conv2dcq_kernel(
    const float* __restrict__ x,
    const float* __restrict__ w,
    const float* __restrict__ bias,
    float* __restrict__ out) {

    // Per-filter packed block of 5 ulonglong2 (16B):
    //   (bias,w0)(w1,w2)(w3,w4)(w5,w6)(w7,w8), each value duplicated (v,v).
    __shared__ ulonglong2 swb[F_OUT * 5];

    const int tid = threadIdx.x;
    {
        u64* sp = reinterpret_cast<u64*>(swb);
        for (int t = tid; t < F_OUT * 10; t += blockDim.x) {
            const int f = t / 10;
            const int k = t % 10;
            const float v = (k == 0) ? bias[f] : w[f * 27 + 18 + (k - 1)];
            sp[t] = pack2(v, v);
        }
    }
    __syncthreads();

    const int idx = blockIdx.x * blockDim.x + tid;

    if (idx < N_MAIN) {
        // ---- main: 4 rows x 2 cols, 16 filters ----
        const int q  = idx / N_SP4;            // filter quarter (slowest)
        const int sp = idx - q * N_SP4;
        const int f0 = q * F_Q;

        const int jp = sp % JP;                // fastest: warp-dense j
        const int t2 = sp / JP;
        const int i4 = t2 % IB4;
        const int n  = t2 / IB4;
        const int i  = i4 * 4;
        const int j  = jp * 2;

        const float* xb = x + (size_t)n * 3 * Hh * Ww + (size_t)i * Ww + j;

        // P[r][b] = (x[i+r][j+b], x[i+r][j+b+1]), r = 0..5
        u64 P[6][3];
        #pragma unroll
        for (int r = 0; r < 6; r++) {
            const float2 lo = *reinterpret_cast<const float2*>(xb + (size_t)r * Ww);
            const float2 hi = *reinterpret_cast<const float2*>(xb + (size_t)r * Ww + 2);
            P[r][0] = pack2(lo.x, lo.y);
            P[r][1] = pack2(lo.y, hi.x);
            P[r][2] = pack2(hi.x, hi.y);
        }

        float* ob = out + (size_t)n * F_OUT * HO * WO
                        + (size_t)f0 * HO * WO
                        + (size_t)i * WO + j;

        const ulonglong2* wq = &swb[f0 * 5];

        #pragma unroll 2
        for (int f = 0; f < F_Q; f++) {
            const ulonglong2 q0 = wq[0], q1 = wq[1], q2 = wq[2],
                             q3 = wq[3], q4 = wq[4];
            const u64 wv[9] = {q0.y, q1.x, q1.y, q2.x, q2.y, q3.x, q3.y, q4.x, q4.y};

            u64 acc[4];
            #pragma unroll
            for (int r = 0; r < 4; r++) acc[r] = q0.x;

            #pragma unroll
            for (int a = 0; a < 3; a++)
                #pragma unroll
                for (int b = 0; b < 3; b++) {
                    const u64 wk = wv[a * 3 + b];
                    #pragma unroll
                    for (int r = 0; r < 4; r++)
                        acc[r] = ffma2(P[r + a][b], wk, acc[r]);
                }

            #pragma unroll
            for (int r = 0; r < 4; r++)
                *reinterpret_cast<u64*>(ob + (size_t)r * WO) = acc[r];

            ob += (size_t)HO * WO;
            wq += 5;
        }
    } else {
        // ---- tail: rows 252..253, 2 rows x 2 cols, 16 filters ----
        const int t0 = idx - N_MAIN;
        const int q  = t0 / N_SPT;
        const int sp = t0 - q * N_SPT;
        const int f0 = q * F_Q;

        const int jp = sp % JP;
        const int n  = sp / JP;
        const int i  = 252;
        const int j  = jp * 2;

        const float* xb = x + (size_t)n * 3 * Hh * Ww + (size_t)i * Ww + j;

        u64 P[4][3];
        #pragma unroll
        for (int r = 0; r < 4; r++) {
            const float2 lo = *reinterpret_cast<const float2*>(xb + (size_t)r * Ww);
            const float2 hi = *reinterpret_cast<const float2*>(xb + (size_t)r * Ww + 2);
            P[r][0] = pack2(lo.x, lo.y);
            P[r][1] = pack2(lo.y, hi.x);
            P[r][2] = pack2(hi.x, hi.y);
        }

        float* ob = out + (size_t)n * F_OUT * HO * WO
                        + (size_t)f0 * HO * WO
                        + (size_t)i * WO + j;

        const ulonglong2* wq = &swb[f0 * 5];

        #pragma unroll 2
        for (int f = 0; f < F_Q; f++) {
            const ulonglong2 q0 = wq[0], q1 = wq[1], q2 = wq[2],
                             q3 = wq[3], q4 = wq[4];
            const u64 wv[9] = {q0.y, q1.x, q1.y, q2.x, q2.y, q3.x, q3.y, q4.x, q4.y};

            u64 a0 = q0.x, a1 = q0.x;
            #pragma unroll
            for (int a = 0; a < 3; a++)
                #pragma unroll
                for (int b = 0; b < 3; b++) {
                    const u64 wk = wv[a * 3 + b];
                    a0 = ffma2(P[a][b],     wk, a0);
                    a1 = ffma2(P[a + 1][b], wk, a1);
                }

            *reinterpret_cast<u64*>(ob)      = a0;
            *reinterpret_cast<u64*>(ob + WO) = a1;

            ob += (size_t)HO * WO;
            wq += 5;
        }
    }
}

extern "C" void kernel_launch(void* const* d_in, const int* in_sizes, int n_in,
                              void* d_out, int out_size) {
    const float* x    = (const float*)d_in[0];
    const float* w    = (const float*)d_in[1];
    const float* bias = (const float*)d_in[2];
    float* out        = (float*)d_out;

    const int block = 128;
    const int grid  = N_TOT / block;    // 4064 exactly
    conv2dcq_kernel<<<grid, block>>>(x, w, bias, out);
}